// round 13
// baseline (speedup 1.0000x reference)
#include <cuda_runtime.h>
#include <cuda_bf16.h>
#include <cstdint>

// Per-pixel dynamic 5x5 conv, channel-shared taps.
// x: [B=8, C=64, H=256, W=256] f32; w: [25, B, 1, H, W] f32
//
// Round 13: round-11 pipelined structure (rolling 3-row window, cross-channel
// row prefetch, parity-split FFMA2/FFMA, 3 CTAs/SM) with CTA-SHARED staging:
// one 20-row x 40-col tile per stage (3200B vs 4x1280B warp-private), 4-stage
// ring. Staging for channel c+3 is issued AFTER channel c's publish barrier,
// which closes the cross-warp overwrite race and cuts fill traffic 37.5%.

#define BB 8
#define HW 65536
#define HH_DIM 256
#define WW_DIM 256
#define TH 16
#define TW 32
#define SMW 40                 // row stride (floats) == 10 float4
#define TROWS 20               // CTA tile rows (16 out + 4 halo)
#define CSTG (TROWS * SMW)     // 800 floats = 3200 B per stage
#define NSLOT4 200             // float4 slots per stage (20 x 10)
#define CPERCTA 32
#define NSTAGE 4

__device__ __forceinline__ void cp_async16(uint32_t saddr, const void* gaddr, int src_size) {
    asm volatile("cp.async.cg.shared.global [%0], [%1], 16, %2;"
                 :: "r"(saddr), "l"(gaddr), "r"(src_size));
}
__device__ __forceinline__ void cp_commit() {
    asm volatile("cp.async.commit_group;");
}
template <int N>
__device__ __forceinline__ void cp_wait() {
    asm volatile("cp.async.wait_group %0;" :: "n"(N));
}

__device__ __forceinline__ uint64_t lds64(uint32_t a) {
    uint64_t v; asm volatile("ld.shared.b64 %0, [%1];" : "=l"(v) : "r"(a)); return v;
}
__device__ __forceinline__ void ffma2(uint64_t& d, uint64_t a, uint64_t b) {
    asm("fma.rn.f32x2 %0, %1, %2, %0;" : "+l"(d) : "l"(a), "l"(b));
}
__device__ __forceinline__ uint64_t addf32x2(uint64_t a, uint64_t b) {
    uint64_t r; asm("add.rn.f32x2 %0, %1, %2;" : "=l"(r) : "l"(a), "l"(b)); return r;
}
__device__ __forceinline__ void unpack2f(uint64_t v, float& lo, float& hi) {
    asm("mov.b64 {%0, %1}, %2;" : "=f"(lo), "=f"(hi) : "l"(v));
}
__device__ __forceinline__ float lo_f(uint64_t v) { float a, b; unpack2f(v, a, b); return a; }
__device__ __forceinline__ float hi_f(uint64_t v) { float a, b; unpack2f(v, a, b); return b; }

__global__ __launch_bounds__(128, 3)
void dynconv5x5_kernel(const float* __restrict__ x,
                       const float* __restrict__ wgt,
                       float* __restrict__ out) {
    __shared__ float sm[NSTAGE][CSTG];   // 4 x 3200 B, CTA-shared

    const int tid  = threadIdx.x;
    const int wid  = tid >> 5;
    const int lane = tid & 31;
    const int qx   = lane & 15;
    const int qy   = lane >> 4;
    const int w0   = blockIdx.x * TW;
    const int h0   = blockIdx.y * TH;
    const int z    = blockIdx.z;
    const int b    = z >> 1;
    const int c0   = (z & 1) * CPERCTA;

    const int trow = wid * 4 + qy * 2;   // quad top row within CTA tile
    const int oh   = h0 + trow;
    const int ow   = w0 + qx * 2;

    // ---- weights, split by tap x-offset parity (100 regs total)
    uint64_t wtp[15], wbp[15];                      // even-ww packed pairs
    float wtsl[10], wtsh[10], wbsl[10], wbsh[10];   // odd-ww scalar halves
#pragma unroll
    for (int r = 0; r < 5; r++) {
#pragma unroll
        for (int ww = 0; ww < 5; ww++) {
            const float* wp = &wgt[(((size_t)(r * 5 + ww) * BB + b) * HH_DIM + oh) * WW_DIM + ow];
            uint64_t t  = *(const uint64_t*)(wp);
            uint64_t bo = *(const uint64_t*)(wp + WW_DIM);
            if ((ww & 1) == 0) {
                wtp[r * 3 + ww / 2] = t;
                wbp[r * 3 + ww / 2] = bo;
            } else {
                int j = r * 2 + (ww == 3);
                unpack2f(t,  wtsl[j], wtsh[j]);
                unpack2f(bo, wbsl[j], wbsh[j]);
            }
        }
    }

    // ---- CTA-shared staging: 200 float4 slots, 2 per thread (tid<72 takes 2)
    int xoff[2];
    int ssz [2];
    int soff[2];
    const bool has2 = (tid < NSLOT4 - 128);   // tid < 72
#pragma unroll
    for (int j = 0; j < 2; j++) {
        int i    = tid + j * 128;             // slot id
        int r    = i / 10;
        int col4 = i - r * 10;
        int gh = h0 + r - 2;
        int gw = w0 - 4 + col4 * 4;
        bool v = (i < NSLOT4) && gh >= 0 && gh < HH_DIM && gw >= 0 && gw < WW_DIM;
        xoff[j] = gh * WW_DIM + gw;
        ssz[j]  = v ? 16 : 0;
        soff[j] = (r * SMW + col4 * 4) * 4;
    }

    const float* xc = x   + ((size_t)b * 64 + c0) * HW;
    float*       ob = out + (((size_t)b * 64 + c0) * HW) + oh * WW_DIM + ow;

    const uint32_t sm0   = (uint32_t)__cvta_generic_to_shared(&sm[0][0]);
    const uint32_t cbase = sm0 + (trow * SMW + (qx * 2 + 2)) * 4;

    // ---- prologue: stage channels 0..2 (3 groups)
#pragma unroll
    for (int p = 0; p < 3; p++) {
        const float* xp = xc + (size_t)p * HW;
        const uint32_t sp = sm0 + p * (CSTG * 4);
        cp_async16(sp + soff[0], xp + xoff[0], ssz[0]);
        if (has2) cp_async16(sp + soff[1], xp + xoff[1], ssz[1]);
        cp_commit();
    }
    cp_wait<2>();          // fill of channel 0 complete
    __syncthreads();       // publish stage 0 CTA-wide

    // rolling 3-row register window; preload rows 0,1 of channel 0
    uint64_t rp[3][3];
#pragma unroll
    for (int r = 0; r < 2; r++) {
        uint32_t a = cbase + r * (SMW * 4);
        rp[r][0] = lds64(a);
        rp[r][1] = lds64(a + 8);
        rp[r][2] = lds64(a + 16);
    }

#pragma unroll 4
    for (int c = 0; c < CPERCTA; c++) {
        const uint32_t sc = cbase + (c & 3) * (CSTG * 4);
        const uint32_t sn = cbase + ((c + 1) & 3) * (CSTG * 4);
        // clamped staging channel (duplicate refills write identical bytes)
        int cs = c + 3; if (cs > CPERCTA - 1) cs = CPERCTA - 1;
        const float*   xs  = xc + (size_t)cs * HW;
        const uint32_t ssb = sm0 + (cs & 3) * (CSTG * 4);

        uint64_t atp = 0, atq = 0, abp = 0, abq = 0;
        float ats0 = 0.f, ats1 = 0.f, abs0 = 0.f, abs1 = 0.f;

#pragma unroll
        for (int r = 0; r < 6; r++) {
            // issue loads for row r+2 of this channel
            if (r < 4) {
                int s2 = (r + 2) % 3;
                uint32_t a = sc + (r + 2) * (SMW * 4);
                rp[s2][0] = lds64(a);
                rp[s2][1] = lds64(a + 8);
                rp[s2][2] = lds64(a + 16);
            }

            // compute row r from slot r%3
            int s = r % 3;
            uint64_t p0 = rp[s][0], p2 = rp[s][1], p4 = rp[s][2];
            float x1 = hi_f(p0);
            float x2 = lo_f(p2);
            float x3 = hi_f(p2);
            float x4 = lo_f(p4);
            if (r < 5) {
                ffma2(atp, p0, wtp[r * 3 + 0]);
                ffma2(atq, p2, wtp[r * 3 + 1]);
                ffma2(atp, p4, wtp[r * 3 + 2]);
                ats0 = fmaf(x1, wtsl[r * 2 + 0], ats0);
                ats1 = fmaf(x2, wtsh[r * 2 + 0], ats1);
                ats0 = fmaf(x3, wtsl[r * 2 + 1], ats0);
                ats1 = fmaf(x4, wtsh[r * 2 + 1], ats1);
            }
            if (r >= 1) {
                int q = r - 1;
                ffma2(abp, p0, wbp[q * 3 + 0]);
                ffma2(abq, p2, wbp[q * 3 + 1]);
                ffma2(abp, p4, wbp[q * 3 + 2]);
                abs0 = fmaf(x1, wbsl[q * 2 + 0], abs0);
                abs1 = fmaf(x2, wbsh[q * 2 + 0], abs1);
                abs0 = fmaf(x3, wbsl[q * 2 + 1], abs0);
                abs1 = fmaf(x4, wbsh[q * 2 + 1], abs1);
            }

            // publish stage for channel c+1 (fills except newest are complete);
            // all warps' reads of stage c-1 precede this barrier -> staging
            // below (which overwrites stage (c-1)&3) is race-free.
            if (r == 3) {
                cp_wait<1>();
                __syncthreads();
            }
            // staging issues AFTER the barrier
            if (r == 4) cp_async16(ssb + soff[0], xs + xoff[0], ssz[0]);
            if (r == 5) {
                if (has2) cp_async16(ssb + soff[1], xs + xoff[1], ssz[1]);
                cp_commit();
            }
            // cross-channel prefetch: rows 0,1 of channel c+1
            if (r >= 4) {
                int s2 = (r + 2) % 3;   // == (r-4)%3, seamless for next channel
                uint32_t a = sn + (r - 4) * (SMW * 4);
                rp[s2][0] = lds64(a);
                rp[s2][1] = lds64(a + 8);
                rp[s2][2] = lds64(a + 16);
            }
        }

        float tl, th, bl, bh;
        unpack2f(addf32x2(atp, atq), tl, th);
        unpack2f(addf32x2(abp, abq), bl, bh);

        float* o = ob + (size_t)c * HW;
        *(float2*)(o)          = make_float2(tl + ats0, th + ats1);
        *(float2*)(o + WW_DIM) = make_float2(bl + abs0, bh + abs1);
    }
}

extern "C" void kernel_launch(void* const* d_in, const int* in_sizes, int n_in,
                              void* d_out, int out_size) {
    const float* x   = (const float*)d_in[0];
    const float* wgt = (const float*)d_in[1];
    float*       out = (float*)d_out;

    dim3 grid(WW_DIM / TW, HH_DIM / TH, BB * 2);   // 2048 blocks
    dim3 block(128);
    dynconv5x5_kernel<<<grid, block>>>(x, wgt, out);
}

// round 14
// speedup vs baseline: 1.0630x; 1.0630x over previous
#include <cuda_runtime.h>
#include <cuda.h>
#include <cuda_bf16.h>
#include <cstdint>

// Per-pixel dynamic 5x5 conv, channel-shared taps.
// x: [B=8, C=64, H=256, W=256] f32; w: [25, B, 1, H, W] f32
//
// Round-11 skeleton (warp-private 4-stage pipelines, rolling 3-row register
// window, cross-channel row prefetch, parity-split FFMA2/FFMA, 3 CTAs/SM)
// with TMA staging: one cp.async.bulk.tensor.3d per warp per channel fills the
// 8x40-float slab (lane 0 issues; per-warp per-stage mbarrier completion).
// Border zero-fill is done by TMA OOB handling (negative coords). No per-lane
// staging instructions, no cp.async, no __syncthreads.

#define BB 8
#define HW 65536
#define HH_DIM 256
#define WW_DIM 256
#define TW 32
#define SMW 40                 // slab row stride (floats) = 160 B = TMA box dim0
#define WROWS 8                // rows per warp slab (4 out + 4 halo)
#define WSTAGE (WROWS * SMW)   // 320 floats = 1280 B per stage
#define TMA_BYTES (WSTAGE * 4)
#define CPERCTA 32
#define NSTAGE 4
#define PFD 3

__device__ __forceinline__ uint64_t lds64(uint32_t a) {
    uint64_t v; asm volatile("ld.shared.b64 %0, [%1];" : "=l"(v) : "r"(a)); return v;
}
__device__ __forceinline__ void ffma2(uint64_t& d, uint64_t a, uint64_t b) {
    asm("fma.rn.f32x2 %0, %1, %2, %0;" : "+l"(d) : "l"(a), "l"(b));
}
__device__ __forceinline__ uint64_t addf32x2(uint64_t a, uint64_t b) {
    uint64_t r; asm("add.rn.f32x2 %0, %1, %2;" : "=l"(r) : "l"(a), "l"(b)); return r;
}
__device__ __forceinline__ void unpack2f(uint64_t v, float& lo, float& hi) {
    asm("mov.b64 {%0, %1}, %2;" : "=f"(lo), "=f"(hi) : "l"(v));
}
__device__ __forceinline__ float lo_f(uint64_t v) { float a, b; unpack2f(v, a, b); return a; }
__device__ __forceinline__ float hi_f(uint64_t v) { float a, b; unpack2f(v, a, b); return b; }

// ---- mbarrier + TMA helpers ----
__device__ __forceinline__ void mbar_init(uint32_t a, uint32_t cnt) {
    asm volatile("mbarrier.init.shared.b64 [%0], %1;" :: "r"(a), "r"(cnt) : "memory");
}
__device__ __forceinline__ void mbar_expect_tx(uint32_t a, uint32_t bytes) {
    asm volatile("mbarrier.arrive.expect_tx.shared.b64 _, [%0], %1;"
                 :: "r"(a), "r"(bytes) : "memory");
}
__device__ __forceinline__ void mbar_wait(uint32_t a, uint32_t parity) {
    asm volatile(
        "{\n\t"
        ".reg .pred P;\n\t"
        "WAIT_%=:\n\t"
        "mbarrier.try_wait.parity.acquire.cta.shared::cta.b64 P, [%0], %1, 0x989680;\n\t"
        "@P bra.uni DONE_%=;\n\t"
        "bra.uni WAIT_%=;\n\t"
        "DONE_%=:\n\t"
        "}"
        :: "r"(a), "r"(parity) : "memory");
}
__device__ __forceinline__ void tma3d(uint32_t dst, const CUtensorMap* m,
                                      int cx, int cy, int cz, uint32_t bar) {
    asm volatile(
        "cp.async.bulk.tensor.3d.shared::cta.global.tile.mbarrier::complete_tx::bytes "
        "[%0], [%1, {%2, %3, %4}], [%5];"
        :: "r"(dst), "l"(m), "r"(cx), "r"(cy), "r"(cz), "r"(bar) : "memory");
}

__global__ __launch_bounds__(128, 3)
void dynconv5x5_kernel(const __grid_constant__ CUtensorMap tmx,
                       const float* __restrict__ wgt,
                       float* __restrict__ out) {
    __shared__ __align__(16) float sm[4][NSTAGE][WSTAGE];   // [warp][stage][slab]
    __shared__ __align__(8)  unsigned long long mb[4][NSTAGE];

    const int tid  = threadIdx.x;
    const int wid  = tid >> 5;
    const int lane = tid & 31;
    const int qx   = lane & 15;
    const int qy   = lane >> 4;
    const int w0   = blockIdx.x * TW;
    const int h0   = blockIdx.y * 16;
    const int z    = blockIdx.z;
    const int b    = z >> 1;
    const int c0   = (z & 1) * CPERCTA;

    const int slab0 = h0 + wid * 4;
    const int oh    = slab0 + qy * 2;
    const int ow    = w0 + qx * 2;
    const int bc0   = b * 64 + c0;

    // ---- per-warp mbarriers (count=1, tx-based completion)
    const uint32_t mb0 = (uint32_t)__cvta_generic_to_shared(&mb[wid][0]);
    if (lane == 0) {
#pragma unroll
        for (int s = 0; s < NSTAGE; s++) mbar_init(mb0 + s * 8, 1);
        asm volatile("fence.proxy.async.shared::cta;" ::: "memory");
    }
    __syncwarp(0xffffffffu);

    // ---- weights, split by tap x-offset parity (100 regs total)
    uint64_t wtp[15], wbp[15];
    float wtsl[10], wtsh[10], wbsl[10], wbsh[10];
#pragma unroll
    for (int r = 0; r < 5; r++) {
#pragma unroll
        for (int ww = 0; ww < 5; ww++) {
            const float* wp = &wgt[(((size_t)(r * 5 + ww) * BB + b) * HH_DIM + oh) * WW_DIM + ow];
            uint64_t t  = *(const uint64_t*)(wp);
            uint64_t bo = *(const uint64_t*)(wp + WW_DIM);
            if ((ww & 1) == 0) {
                wtp[r * 3 + ww / 2] = t;
                wbp[r * 3 + ww / 2] = bo;
            } else {
                int j = r * 2 + (ww == 3);
                unpack2f(t,  wtsl[j], wtsh[j]);
                unpack2f(bo, wbsl[j], wbsh[j]);
            }
        }
    }

    float* ob = out + (((size_t)bc0) * HW) + oh * WW_DIM + ow;

    const uint32_t wbase = (uint32_t)__cvta_generic_to_shared(&sm[wid][0][0]);
    const uint32_t cbase = wbase + ((qy * 2) * SMW + (qx * 2 + 2)) * 4;
    const int cx = w0 - 4;        // TMA handles negative coords: zero-fill
    const int cy = slab0 - 2;

    // ---- prologue: TMA-stage channels 0..PFD-1
    if (lane == 0) {
#pragma unroll
        for (int p = 0; p < PFD; p++) {
            mbar_expect_tx(mb0 + p * 8, TMA_BYTES);
            tma3d(wbase + p * TMA_BYTES, &tmx, cx, cy, bc0 + p, mb0 + p * 8);
        }
    }
    __syncwarp(0xffffffffu);

    // wait channel 0 (stage 0, generation 0 -> parity 0), preload rows 0,1
    mbar_wait(mb0, 0);
    uint64_t rp[3][3];
#pragma unroll
    for (int r = 0; r < 2; r++) {
        uint32_t a = cbase + r * (SMW * 4);
        rp[r][0] = lds64(a);
        rp[r][1] = lds64(a + 8);
        rp[r][2] = lds64(a + 16);
    }

#pragma unroll 4
    for (int c = 0; c < CPERCTA; c++) {
        const uint32_t sc = cbase + (c & 3) * TMA_BYTES;
        const uint32_t sn = cbase + ((c + 1) & 3) * TMA_BYTES;

        uint64_t atp = 0, atq = 0, abp = 0, abq = 0;
        float ats0 = 0.f, ats1 = 0.f, abs0 = 0.f, abs1 = 0.f;

#pragma unroll
        for (int r = 0; r < 6; r++) {
            // issue loads for row r+2 of this channel
            if (r < 4) {
                int s2 = (r + 2) % 3;
                uint32_t a = sc + (r + 2) * (SMW * 4);
                rp[s2][0] = lds64(a);
                rp[s2][1] = lds64(a + 8);
                rp[s2][2] = lds64(a + 16);
            }

            // compute row r from slot r%3
            int s = r % 3;
            uint64_t p0 = rp[s][0], p2 = rp[s][1], p4 = rp[s][2];
            float x1 = hi_f(p0);
            float x2 = lo_f(p2);
            float x3 = hi_f(p2);
            float x4 = lo_f(p4);
            if (r < 5) {
                ffma2(atp, p0, wtp[r * 3 + 0]);
                ffma2(atq, p2, wtp[r * 3 + 1]);
                ffma2(atp, p4, wtp[r * 3 + 2]);
                ats0 = fmaf(x1, wtsl[r * 2 + 0], ats0);
                ats1 = fmaf(x2, wtsh[r * 2 + 0], ats1);
                ats0 = fmaf(x3, wtsl[r * 2 + 1], ats0);
                ats1 = fmaf(x4, wtsh[r * 2 + 1], ats1);
            }
            if (r >= 1) {
                int q = r - 1;
                ffma2(abp, p0, wbp[q * 3 + 0]);
                ffma2(abq, p2, wbp[q * 3 + 1]);
                ffma2(abp, p4, wbp[q * 3 + 2]);
                abs0 = fmaf(x1, wbsl[q * 2 + 0], abs0);
                abs1 = fmaf(x2, wbsh[q * 2 + 0], abs1);
                abs0 = fmaf(x3, wbsl[q * 2 + 1], abs0);
                abs1 = fmaf(x4, wbsh[q * 2 + 1], abs1);
            }

            // publish next channel's stage (generation (c+1)>>2 -> its parity)
            if (r == 3 && c + 1 < CPERCTA) {
                mbar_wait(mb0 + ((c + 1) & 3) * 8, ((c + 1) >> 2) & 1);
            }
            // TMA for channel c+PFD: overwrites stage (c-1)&3, whose last read
            // (by this warp) was channel c-1 r==3 -> program-order safe.
            if (r == 4 && lane == 0 && c + PFD < CPERCTA) {
                int cs = c + PFD;
                uint32_t bar = mb0 + (cs & 3) * 8;
                mbar_expect_tx(bar, TMA_BYTES);
                tma3d(wbase + (cs & 3) * TMA_BYTES, &tmx, cx, cy, bc0 + cs, bar);
            }
            // cross-channel prefetch: rows 0,1 of channel c+1 (stale read at
            // c==31 is harmless: values never used, no fill in flight there)
            if (r >= 4) {
                int s2 = (r + 2) % 3;
                uint32_t a = sn + (r - 4) * (SMW * 4);
                rp[s2][0] = lds64(a);
                rp[s2][1] = lds64(a + 8);
                rp[s2][2] = lds64(a + 16);
            }
        }

        float tl, th, bl, bh;
        unpack2f(addf32x2(atp, atq), tl, th);
        unpack2f(addf32x2(abp, abq), bl, bh);

        float* o = ob + (size_t)c * HW;
        *(float2*)(o)          = make_float2(tl + ats0, th + ats1);
        *(float2*)(o + WW_DIM) = make_float2(bl + abs0, bh + abs1);
    }
}

// ---- host: build the TMA descriptor without requiring -lcuda ----
typedef CUresult (*EncodeTiledFn)(
    CUtensorMap*, CUtensorMapDataType, cuuint32_t, void*,
    const cuuint64_t*, const cuuint64_t*, const cuuint32_t*, const cuuint32_t*,
    CUtensorMapInterleave, CUtensorMapSwizzle, CUtensorMapL2promotion,
    CUtensorMapFloatOOBfill);

extern "C" void kernel_launch(void* const* d_in, const int* in_sizes, int n_in,
                              void* d_out, int out_size) {
    const float* x   = (const float*)d_in[0];
    const float* wgt = (const float*)d_in[1];
    float*       out = (float*)d_out;

    EncodeTiledFn encode = nullptr;
    cudaDriverEntryPointQueryResult qres;
    cudaGetDriverEntryPointByVersion("cuTensorMapEncodeTiled", (void**)&encode,
                                     12000, cudaEnableDefault, &qres);

    CUtensorMap tmx;
    cuuint64_t gdim[3]    = {WW_DIM, HH_DIM, (cuuint64_t)BB * 64};
    cuuint64_t gstride[2] = {WW_DIM * 4ull, (cuuint64_t)HW * 4ull};
    cuuint32_t box[3]     = {SMW, WROWS, 1};
    cuuint32_t estr[3]    = {1, 1, 1};
    encode(&tmx, CU_TENSOR_MAP_DATA_TYPE_FLOAT32, 3, (void*)x,
           gdim, gstride, box, estr,
           CU_TENSOR_MAP_INTERLEAVE_NONE, CU_TENSOR_MAP_SWIZZLE_NONE,
           CU_TENSOR_MAP_L2_PROMOTION_L2_128B, CU_TENSOR_MAP_FLOAT_OOB_FILL_NONE);

    dim3 grid(WW_DIM / TW, HH_DIM / 16, BB * 2);   // 2048 blocks
    dim3 block(128);
    dynconv5x5_kernel<<<grid, block>>>(tmx, wgt, out);
}

// round 15
// speedup vs baseline: 1.1493x; 1.0812x over previous
#include <cuda_runtime.h>
#include <cuda_bf16.h>
#include <cstdint>

// Per-pixel dynamic 5x5 conv, channel-shared taps.
// x: [B=8, C=64, H=256, W=256] f32; w: [25, B, 1, H, W] f32
//
// Round-11 skeleton (warp-private cp.async pipelines, 2x2 quad/thread,
// parity-split FFMA2/FFMA, 3 CTAs/SM) + TWO CHANNELS PER ITERATION:
// each warp computes channels 2i,2i+1 back-to-back from an 8-slab private
// ring, doubling independent FMA/LDS streams per warp. Staging runs 6
// channels ahead (wait_group<4> = 2 iterations of fills in flight).

#define BB 8
#define HW 65536
#define HH_DIM 256
#define WW_DIM 256
#define TW 32
#define SMW 40                 // slab row stride (floats)
#define WROWS 8                // rows per warp slab (4 out + 4 halo)
#define WSTAGE (WROWS * SMW)   // 320 floats = 1280 B per slab
#define SLAB_B (WSTAGE * 4)
#define NSLOT4 80              // float4 slots per slab
#define CPERCTA 32
#define NSTAGE 8               // slabs in the per-warp ring

__device__ __forceinline__ void cp_async16(uint32_t saddr, const void* gaddr, int src_size) {
    asm volatile("cp.async.cg.shared.global [%0], [%1], 16, %2;"
                 :: "r"(saddr), "l"(gaddr), "r"(src_size));
}
__device__ __forceinline__ void cp_commit() {
    asm volatile("cp.async.commit_group;");
}
template <int N>
__device__ __forceinline__ void cp_wait() {
    asm volatile("cp.async.wait_group %0;" :: "n"(N));
}

__device__ __forceinline__ uint64_t lds64(uint32_t a) {
    uint64_t v; asm volatile("ld.shared.b64 %0, [%1];" : "=l"(v) : "r"(a)); return v;
}
__device__ __forceinline__ void ffma2(uint64_t& d, uint64_t a, uint64_t b) {
    asm("fma.rn.f32x2 %0, %1, %2, %0;" : "+l"(d) : "l"(a), "l"(b));
}
__device__ __forceinline__ uint64_t addf32x2(uint64_t a, uint64_t b) {
    uint64_t r; asm("add.rn.f32x2 %0, %1, %2;" : "=l"(r) : "l"(a), "l"(b)); return r;
}
__device__ __forceinline__ void unpack2f(uint64_t v, float& lo, float& hi) {
    asm("mov.b64 {%0, %1}, %2;" : "=f"(lo), "=f"(hi) : "l"(v));
}
__device__ __forceinline__ float lo_f(uint64_t v) { float a, b; unpack2f(v, a, b); return a; }
__device__ __forceinline__ float hi_f(uint64_t v) { float a, b; unpack2f(v, a, b); return b; }

// one channel's 25-tap quad conv from a slab; writes the 2x2 output
__device__ __forceinline__ void conv_channel(
    uint32_t sbase,
    const uint64_t* __restrict__ wtp, const uint64_t* __restrict__ wbp,
    const float* __restrict__ wtsl, const float* __restrict__ wtsh,
    const float* __restrict__ wbsl, const float* __restrict__ wbsh,
    float* __restrict__ o)
{
    uint64_t atp = 0, atq = 0, abp = 0, abq = 0;
    float ats0 = 0.f, ats1 = 0.f, abs0 = 0.f, abs1 = 0.f;
#pragma unroll
    for (int r = 0; r < 6; r++) {
        uint32_t base = sbase + r * (SMW * 4);
        uint64_t p0 = lds64(base);
        uint64_t p2 = lds64(base + 8);
        uint64_t p4 = lds64(base + 16);
        float x1 = hi_f(p0);
        float x2 = lo_f(p2);
        float x3 = hi_f(p2);
        float x4 = lo_f(p4);
        if (r < 5) {
            ffma2(atp, p0, wtp[r * 3 + 0]);
            ffma2(atq, p2, wtp[r * 3 + 1]);
            ffma2(atp, p4, wtp[r * 3 + 2]);
            ats0 = fmaf(x1, wtsl[r * 2 + 0], ats0);
            ats1 = fmaf(x2, wtsh[r * 2 + 0], ats1);
            ats0 = fmaf(x3, wtsl[r * 2 + 1], ats0);
            ats1 = fmaf(x4, wtsh[r * 2 + 1], ats1);
        }
        if (r >= 1) {
            int q = r - 1;
            ffma2(abp, p0, wbp[q * 3 + 0]);
            ffma2(abq, p2, wbp[q * 3 + 1]);
            ffma2(abp, p4, wbp[q * 3 + 2]);
            abs0 = fmaf(x1, wbsl[q * 2 + 0], abs0);
            abs1 = fmaf(x2, wbsh[q * 2 + 0], abs1);
            abs0 = fmaf(x3, wbsl[q * 2 + 1], abs0);
            abs1 = fmaf(x4, wbsh[q * 2 + 1], abs1);
        }
    }
    float tl, th, bl, bh;
    unpack2f(addf32x2(atp, atq), tl, th);
    unpack2f(addf32x2(abp, abq), bl, bh);
    *(float2*)(o)          = make_float2(tl + ats0, th + ats1);
    *(float2*)(o + WW_DIM) = make_float2(bl + abs0, bh + abs1);
}

__global__ __launch_bounds__(128, 3)
void dynconv5x5_kernel(const float* __restrict__ x,
                       const float* __restrict__ wgt,
                       float* __restrict__ out) {
    __shared__ float sm[4][NSTAGE][WSTAGE];   // 40 KB: [warp][slab][data]

    const int tid  = threadIdx.x;
    const int wid  = tid >> 5;
    const int lane = tid & 31;
    const int qx   = lane & 15;
    const int qy   = lane >> 4;
    const int w0   = blockIdx.x * TW;
    const int h0   = blockIdx.y * 16;
    const int z    = blockIdx.z;
    const int b    = z >> 1;
    const int c0   = (z & 1) * CPERCTA;

    const int slab0 = h0 + wid * 4;
    const int oh    = slab0 + qy * 2;
    const int ow    = w0 + qx * 2;

    // ---- weights, parity-split (100 regs)
    uint64_t wtp[15], wbp[15];
    float wtsl[10], wtsh[10], wbsl[10], wbsh[10];
#pragma unroll
    for (int r = 0; r < 5; r++) {
#pragma unroll
        for (int ww = 0; ww < 5; ww++) {
            const float* wp = &wgt[(((size_t)(r * 5 + ww) * BB + b) * HH_DIM + oh) * WW_DIM + ow];
            uint64_t t  = *(const uint64_t*)(wp);
            uint64_t bo = *(const uint64_t*)(wp + WW_DIM);
            if ((ww & 1) == 0) {
                wtp[r * 3 + ww / 2] = t;
                wbp[r * 3 + ww / 2] = bo;
            } else {
                int j = r * 2 + (ww == 3);
                unpack2f(t,  wtsl[j], wtsh[j]);
                unpack2f(bo, wbsl[j], wbsh[j]);
            }
        }
    }

    // ---- 16B staging slots (80 float4 = 8 rows x 10; col c <-> gw w0-4+c)
    int xoff[3];
    int ssz [3];
    int soff[3];
    const bool has3 = (lane < 16);
#pragma unroll
    for (int j = 0; j < 3; j++) {
        int i    = lane + j * 32;
        int r    = i / 10;
        int col4 = i - r * 10;
        int gh = slab0 + r - 2;
        int gw = w0 - 4 + col4 * 4;
        bool v = (i < NSLOT4) && gh >= 0 && gh < HH_DIM && gw >= 0 && gw < WW_DIM;
        xoff[j] = gh * WW_DIM + gw;
        ssz[j]  = v ? 16 : 0;
        soff[j] = (r * SMW + col4 * 4) * 4;
    }

    const float* xc = x   + ((size_t)b * 64 + c0) * HW;
    float*       ob = out + (((size_t)b * 64 + c0) * HW) + oh * WW_DIM + ow;

    const uint32_t wbase = (uint32_t)__cvta_generic_to_shared(&sm[wid][0][0]);
    const uint32_t cbase = wbase + ((qy * 2) * SMW + (qx * 2 + 2)) * 4;

    // ---- prologue: stage channels 0..5 into slabs 0..5 (one group each)
#pragma unroll
    for (int p = 0; p < 6; p++) {
        const float* xp = xc + (size_t)p * HW;
        const uint32_t sp = wbase + p * SLAB_B;
        cp_async16(sp + soff[0], xp + xoff[0], ssz[0]);
        cp_async16(sp + soff[1], xp + xoff[1], ssz[1]);
        if (has3) cp_async16(sp + soff[2], xp + xoff[2], ssz[2]);
        cp_commit();
    }

#pragma unroll 4
    for (int it = 0; it < CPERCTA / 2; it++) {
        const int cA = 2 * it;
        const int cB = cA + 1;

        // fills for cA,cB complete when <=4 newer groups remain outstanding
        if (cA + 6 < CPERCTA) cp_wait<4>(); else cp_wait<0>();
        __syncwarp(0xffffffffu);

        conv_channel(cbase + (cA & 7) * SLAB_B, wtp, wbp, wtsl, wtsh, wbsl, wbsh,
                     ob + (size_t)cA * HW);
        conv_channel(cbase + (cB & 7) * SLAB_B, wtp, wbp, wtsl, wtsh, wbsl, wbsh,
                     ob + (size_t)cB * HW);

        // stage channels cA+6, cB+6 (overwrite slabs last read 3 iters ago)
        if (cA + 6 < CPERCTA) {
#pragma unroll
            for (int u = 0; u < 2; u++) {
                int cs = cA + 6 + u;
                const float* xs = xc + (size_t)cs * HW;
                const uint32_t sp = wbase + (cs & 7) * SLAB_B;
                cp_async16(sp + soff[0], xs + xoff[0], ssz[0]);
                cp_async16(sp + soff[1], xs + xoff[1], ssz[1]);
                if (has3) cp_async16(sp + soff[2], xs + xoff[2], ssz[2]);
                cp_commit();
            }
        }
    }
}

extern "C" void kernel_launch(void* const* d_in, const int* in_sizes, int n_in,
                              void* d_out, int out_size) {
    const float* x   = (const float*)d_in[0];
    const float* wgt = (const float*)d_in[1];
    float*       out = (float*)d_out;

    dim3 grid(WW_DIM / TW, HH_DIM / 16, BB * 2);   // 2048 blocks
    dim3 block(128);
    dynconv5x5_kernel<<<grid, block>>>(x, wgt, out);
}